// round 6
// baseline (speedup 1.0000x reference)
#include <cuda_runtime.h>
#include <cuda_bf16.h>
#include <math.h>
#include <stdint.h>

#define NP 100000
#define ND 50000
#define DIM 128
#define NE 600000
#define TILE_M 64
#define ASTRIDE 136   // bf16 elements per smem row (128 + 8 pad)

// ---------------- scratch (static device globals; no allocation allowed) ----
__device__ int   g_deg_pd_src[NP];
__device__ int   g_deg_pd_dst[ND];
__device__ int   g_deg_dp_src[ND];
__device__ int   g_deg_dp_dst[NP];
__device__ float g_rs_pd_src[NP];
__device__ float g_rs_pd_dst[ND];
__device__ float g_rs_dp_src[ND];
__device__ float g_rs_dp_dst[NP];
__device__ int   g_off_pd[ND + 1];
__device__ int   g_off_dp[NP + 1];
__device__ int   g_cur_pd[ND];
__device__ int   g_cur_dp[NP];
__device__ int   g_idx_pd[NE];
__device__ int   g_idx_dp[NE];
__device__ int   g_bsums_pd[256];
__device__ int   g_bsums_dp[256];
__device__ float g_hd1[(size_t)ND * DIM];
__device__ float g_hd2[(size_t)ND * DIM];
__device__ float g_hp1[(size_t)NP * DIM];
__device__ float g_hp2[(size_t)NP * DIM];
// B (= W^T) bf16 hi/lo images, plain [n][k] row-major: 6 x (32KB hi + 32KB lo)
__device__ unsigned char g_Bimg[6 * 65536];

// ---------------- helpers ----------------
__device__ __forceinline__ uint32_t smem_u32(const void* p) {
    uint32_t a;
    asm("{ .reg .u64 t; cvta.to.shared.u64 t, %1; cvt.u32.u64 %0, t; }" : "=r"(a) : "l"(p));
    return a;
}

__device__ __forceinline__ void ldsm_x4(uint32_t* r, uint32_t addr) {
    asm volatile("ldmatrix.sync.aligned.m8n8.x4.shared.b16 {%0,%1,%2,%3}, [%4];"
                 : "=r"(r[0]), "=r"(r[1]), "=r"(r[2]), "=r"(r[3]) : "r"(addr));
}

__device__ __forceinline__ void mma_bf16(float* c, const uint32_t* a, const uint32_t* b) {
    asm volatile("mma.sync.aligned.m16n8k16.row.col.f32.bf16.bf16.f32 "
                 "{%0,%1,%2,%3}, {%4,%5,%6,%7}, {%8,%9}, {%0,%1,%2,%3};"
                 : "+f"(c[0]), "+f"(c[1]), "+f"(c[2]), "+f"(c[3])
                 : "r"(a[0]), "r"(a[1]), "r"(a[2]), "r"(a[3]), "r"(b[0]), "r"(b[1]));
}

__device__ __forceinline__ uint32_t pack_bf2(float a, float b) {
    __nv_bfloat162 t = __floats2bfloat162_rn(a, b);
    return *reinterpret_cast<uint32_t*>(&t);
}

// ---------------- preprocessing kernels (unchanged from R2) ----------------
__global__ void hist_kernel(const int* __restrict__ pd_src, const int* __restrict__ pd_dst,
                            const int* __restrict__ dp_src, const int* __restrict__ dp_dst) {
    int i = blockIdx.x * blockDim.x + threadIdx.x;
    if (i < NE) {
        atomicAdd(&g_deg_pd_src[pd_src[i]], 1);
        atomicAdd(&g_deg_pd_dst[pd_dst[i]], 1);
        atomicAdd(&g_deg_dp_src[dp_src[i]], 1);
        atomicAdd(&g_deg_dp_dst[dp_dst[i]], 1);
    }
}

__global__ void rs_kernel() {
    int i = blockIdx.x * blockDim.x + threadIdx.x;
    if (i < NP) {
        g_rs_pd_src[i] = rsqrtf((float)max(g_deg_pd_src[i], 1));
        g_rs_dp_dst[i] = rsqrtf((float)max(g_deg_dp_dst[i], 1));
    }
    if (i < ND) {
        g_rs_pd_dst[i] = rsqrtf((float)max(g_deg_pd_dst[i], 1));
        g_rs_dp_src[i] = rsqrtf((float)max(g_deg_dp_src[i], 1));
    }
}

__global__ void scan_partial(const int* __restrict__ counts, int n, int* __restrict__ bsums) {
    __shared__ int sh[1024];
    int i = blockIdx.x * 1024 + threadIdx.x;
    sh[threadIdx.x] = (i < n) ? counts[i] : 0;
    __syncthreads();
    for (int d = 512; d > 0; d >>= 1) {
        if (threadIdx.x < d) sh[threadIdx.x] += sh[threadIdx.x + d];
        __syncthreads();
    }
    if (threadIdx.x == 0) bsums[blockIdx.x] = sh[0];
}

__global__ void scan_bsums_exclusive(int* __restrict__ a, int n) {
    __shared__ int sh[1024];
    int t = threadIdx.x;
    int v = (t < n) ? a[t] : 0;
    sh[t] = v;
    __syncthreads();
    for (int d = 1; d < 1024; d <<= 1) {
        int add = (t >= d) ? sh[t - d] : 0;
        __syncthreads();
        sh[t] += add;
        __syncthreads();
    }
    if (t < n) a[t] = sh[t] - v;
}

__global__ void scan_write(const int* __restrict__ counts, int n,
                           const int* __restrict__ bsums, int* __restrict__ offsets,
                           int* __restrict__ cursor) {
    __shared__ int sh[1024];
    int i = blockIdx.x * 1024 + threadIdx.x;
    int v = (i < n) ? counts[i] : 0;
    sh[threadIdx.x] = v;
    __syncthreads();
    for (int d = 1; d < 1024; d <<= 1) {
        int add = (threadIdx.x >= d) ? sh[threadIdx.x - d] : 0;
        __syncthreads();
        sh[threadIdx.x] += add;
        __syncthreads();
    }
    int base = bsums[blockIdx.x];
    if (i < n) {
        int off = base + sh[threadIdx.x] - v;
        offsets[i] = off;
        cursor[i]  = off;
    }
    if (i == n - 1) offsets[n] = base + sh[threadIdx.x];
}

__global__ void scatter_kernel(const int* __restrict__ src, const int* __restrict__ dst,
                               int* __restrict__ cursor, int* __restrict__ csr_idx) {
    int i = blockIdx.x * blockDim.x + threadIdx.x;
    if (i < NE) {
        int p = atomicAdd(&cursor[dst[i]], 1);
        csr_idx[p] = src[i];
    }
}

// ---------------- build B (= W^T) bf16 hi/lo, plain [n][k] row-major -------
__global__ void build_B(const float* W0, const float* W1, const float* W2,
                        const float* W3, const float* W4, const float* W5) {
    const float* Ws[6] = {W0, W1, W2, W3, W4, W5};
    const float* W = Ws[blockIdx.x];
    __nv_bfloat16* hi = (__nv_bfloat16*)(g_Bimg + (size_t)blockIdx.x * 65536);
    __nv_bfloat16* lo = hi + DIM * DIM;
    for (int e = threadIdx.x; e < DIM * DIM; e += blockDim.x) {
        int k = e >> 7, n = e & 127;
        float v = W[e];  // W[k*128 + n]
        __nv_bfloat16 hb = __float2bfloat16_rn(v);
        hi[n * DIM + k] = hb;
        lo[n * DIM + k] = __float2bfloat16_rn(v - __bfloat162float(hb));
    }
}

// ---------------- fused gconv: gather + HMMA GEMM + bias + relu ------------
// 256 threads (8 warps) per 64-row tile.
// smem: A_hi[64][136], A_lo[64][136], B_hi[128][136], B_lo[128][136] (bf16)
#define SM_AHI 0
#define SM_ALO (TILE_M * ASTRIDE * 2)                    // 17408
#define SM_BHI (2 * TILE_M * ASTRIDE * 2)                // 34816
#define SM_BLO (SM_BHI + DIM * ASTRIDE * 2)              // 69632
#define GCONV_SMEM (SM_BLO + DIM * ASTRIDE * 2)          // 104448

__global__ __launch_bounds__(256, 2) void gconv_hmma(
    const float* __restrict__ x,
    const int* __restrict__ off,
    const int* __restrict__ idx,
    const float* __restrict__ rs_src,
    const float* __restrict__ rs_dst,
    const unsigned char* __restrict__ Bimg,
    const float* __restrict__ bias,
    float* __restrict__ out,
    int n_dst) {
    extern __shared__ char smem[];
    const uint32_t sbase = smem_u32(smem);
    const int tid = threadIdx.x;
    const int lane = tid & 31, wid = tid >> 5;
    const int row0 = blockIdx.x * TILE_M;

    // ---- load B hi/lo into padded smem ----
    {
        const uint4* bsrc = (const uint4*)Bimg;  // 2048 uint4 hi, then 2048 lo
        #pragma unroll
        for (int ii = 0; ii < 8; ii++) {
            int i = tid + ii * 256;
            int n = i >> 4;                 // (i*8)/128
            int k = (i << 3) & 127;         // (i*8)%128
            *(uint4*)(smem + SM_BHI + n * (ASTRIDE * 2) + k * 2) = bsrc[i];
            *(uint4*)(smem + SM_BLO + n * (ASTRIDE * 2) + k * 2) = bsrc[2048 + i];
        }
    }

    // ---- gather: row = tid&63, k-quarter = tid>>6 (32 cols) ----
    {
        const int row = tid & 63;
        const int kbase = (tid >> 6) * 32;
        const int j = row0 + row;
        int e0 = 0, e1 = 0;
        float rdst = 0.0f;
        if (j < n_dst) {
            e0 = off[j];
            e1 = off[j + 1];
            rdst = rs_dst[j];
        }
        float4 acc[8];
        #pragma unroll
        for (int i = 0; i < 8; i++) acc[i] = make_float4(0.f, 0.f, 0.f, 0.f);
        for (int e = e0; e < e1; e++) {
            int s = __ldg(&idx[e]);
            float r = __ldg(&rs_src[s]);
            const float4* xp = (const float4*)(x + (size_t)s * DIM + kbase);
            #pragma unroll
            for (int i = 0; i < 8; i++) {
                float4 v = __ldg(&xp[i]);
                acc[i].x += r * v.x;
                acc[i].y += r * v.y;
                acc[i].z += r * v.z;
                acc[i].w += r * v.w;
            }
        }
        uint32_t h[16], l[16];
        #pragma unroll
        for (int i = 0; i < 8; i++) {
            float v0 = acc[i].x * rdst, v1 = acc[i].y * rdst;
            float v2 = acc[i].z * rdst, v3 = acc[i].w * rdst;
            float h0 = __bfloat162float(__float2bfloat16_rn(v0));
            float h1 = __bfloat162float(__float2bfloat16_rn(v1));
            float h2 = __bfloat162float(__float2bfloat16_rn(v2));
            float h3 = __bfloat162float(__float2bfloat16_rn(v3));
            h[2 * i]     = pack_bf2(v0, v1);
            h[2 * i + 1] = pack_bf2(v2, v3);
            l[2 * i]     = pack_bf2(v0 - h0, v1 - h1);
            l[2 * i + 1] = pack_bf2(v2 - h2, v3 - h3);
        }
        char* ah = smem + SM_AHI + row * (ASTRIDE * 2) + kbase * 2;
        char* al = smem + SM_ALO + row * (ASTRIDE * 2) + kbase * 2;
        #pragma unroll
        for (int q = 0; q < 4; q++) {
            ((uint4*)ah)[q] = make_uint4(h[4 * q], h[4 * q + 1], h[4 * q + 2], h[4 * q + 3]);
            ((uint4*)al)[q] = make_uint4(l[4 * q], l[4 * q + 1], l[4 * q + 2], l[4 * q + 3]);
        }
    }
    __syncthreads();

    // ---- GEMM: warp (wr=wid&1, wc=wid>>1) computes 32x32 tile ----
    const int m0 = (wid & 1) * 32;
    const int n0 = (wid >> 1) * 32;
    float c[2][4][4];
    #pragma unroll
    for (int mt = 0; mt < 2; mt++)
        #pragma unroll
        for (int nt = 0; nt < 4; nt++)
            #pragma unroll
            for (int q = 0; q < 4; q++) c[mt][nt][q] = 0.0f;

    // ldmatrix address offsets (element coords)
    const int a_row = (lane & 15);                  // + m0 + mt*16
    const int a_kof = (lane >> 4) << 3;             // 0 or 8
    const int b_row = (lane & 7) + ((lane & 16) >> 1);  // + n0 + p*16
    const int b_kof = (lane & 8);                   // 0 or 8

    #pragma unroll
    for (int kt = 0; kt < 8; kt++) {
        const int k0 = kt * 16;
        uint32_t ah[2][4], al[2][4], bh[2][4], bl[2][4];
        #pragma unroll
        for (int mt = 0; mt < 2; mt++) {
            uint32_t ro = (uint32_t)((m0 + mt * 16 + a_row) * (ASTRIDE * 2) + (k0 + a_kof) * 2);
            ldsm_x4(ah[mt], sbase + SM_AHI + ro);
            ldsm_x4(al[mt], sbase + SM_ALO + ro);
        }
        #pragma unroll
        for (int p = 0; p < 2; p++) {
            uint32_t ro = (uint32_t)((n0 + p * 16 + b_row) * (ASTRIDE * 2) + (k0 + b_kof) * 2);
            ldsm_x4(bh[p], sbase + SM_BHI + ro);
            ldsm_x4(bl[p], sbase + SM_BLO + ro);
        }
        #pragma unroll
        for (int mt = 0; mt < 2; mt++) {
            #pragma unroll
            for (int p = 0; p < 2; p++) {
                #pragma unroll
                for (int hh = 0; hh < 2; hh++) {
                    float* cc = c[mt][p * 2 + hh];
                    mma_bf16(cc, ah[mt], &bh[p][2 * hh]);   // A_hi * B_hi
                    mma_bf16(cc, al[mt], &bh[p][2 * hh]);   // A_lo * B_hi
                    mma_bf16(cc, ah[mt], &bl[p][2 * hh]);   // A_hi * B_lo
                }
            }
        }
    }

    // ---- epilogue: bias + relu + store ----
    #pragma unroll
    for (int mt = 0; mt < 2; mt++) {
        const int r0g = row0 + m0 + mt * 16 + (lane >> 2);
        const int r1g = r0g + 8;
        #pragma unroll
        for (int nt = 0; nt < 4; nt++) {
            const int col = n0 + nt * 8 + (lane & 3) * 2;
            float b0 = __ldg(&bias[col]), b1 = __ldg(&bias[col + 1]);
            if (r0g < n_dst) {
                float2 o;
                o.x = fmaxf(c[mt][nt][0] + b0, 0.f);
                o.y = fmaxf(c[mt][nt][1] + b1, 0.f);
                *(float2*)(out + (size_t)r0g * DIM + col) = o;
            }
            if (r1g < n_dst) {
                float2 o;
                o.x = fmaxf(c[mt][nt][2] + b0, 0.f);
                o.y = fmaxf(c[mt][nt][3] + b1, 0.f);
                *(float2*)(out + (size_t)r1g * DIM + col) = o;
            }
        }
    }
}

// ---------------- host launch ----------------
extern "C" void kernel_launch(void* const* d_in, const int* in_sizes, int n_in,
                              void* d_out, int out_size) {
    const float* h_p    = (const float*)d_in[0];
    const float* h_d    = (const float*)d_in[1];
    const int*   pd_src = (const int*)d_in[2];
    const int*   pd_dst = (const int*)d_in[3];
    const int*   dp_src = (const int*)d_in[4];
    const int*   dp_dst = (const int*)d_in[5];
    const float* W1_pd  = (const float*)d_in[6];
    const float* b1_pd  = (const float*)d_in[7];
    const float* W1_dp  = (const float*)d_in[8];
    const float* b1_dp  = (const float*)d_in[9];
    const float* W2_pd  = (const float*)d_in[10];
    const float* b2_pd  = (const float*)d_in[11];
    const float* W2_dp  = (const float*)d_in[12];
    const float* b2_dp  = (const float*)d_in[13];
    const float* W3_pd  = (const float*)d_in[14];
    const float* b3_pd  = (const float*)d_in[15];
    const float* W3_dp  = (const float*)d_in[16];
    const float* b3_dp  = (const float*)d_in[17];

    float* out_p = (float*)d_out;
    float* out_d = (float*)d_out + (size_t)NP * DIM;

    void *p_deg_pd_src, *p_deg_pd_dst, *p_deg_dp_src, *p_deg_dp_dst;
    void *p_rs_pd_src, *p_rs_pd_dst, *p_rs_dp_src, *p_rs_dp_dst;
    void *p_off_pd, *p_off_dp, *p_cur_pd, *p_cur_dp, *p_idx_pd, *p_idx_dp;
    void *p_bsums_pd, *p_bsums_dp, *p_hd1, *p_hd2, *p_hp1, *p_hp2, *p_Bimg;
    cudaGetSymbolAddress(&p_deg_pd_src, g_deg_pd_src);
    cudaGetSymbolAddress(&p_deg_pd_dst, g_deg_pd_dst);
    cudaGetSymbolAddress(&p_deg_dp_src, g_deg_dp_src);
    cudaGetSymbolAddress(&p_deg_dp_dst, g_deg_dp_dst);
    cudaGetSymbolAddress(&p_rs_pd_src, g_rs_pd_src);
    cudaGetSymbolAddress(&p_rs_pd_dst, g_rs_pd_dst);
    cudaGetSymbolAddress(&p_rs_dp_src, g_rs_dp_src);
    cudaGetSymbolAddress(&p_rs_dp_dst, g_rs_dp_dst);
    cudaGetSymbolAddress(&p_off_pd, g_off_pd);
    cudaGetSymbolAddress(&p_off_dp, g_off_dp);
    cudaGetSymbolAddress(&p_cur_pd, g_cur_pd);
    cudaGetSymbolAddress(&p_cur_dp, g_cur_dp);
    cudaGetSymbolAddress(&p_idx_pd, g_idx_pd);
    cudaGetSymbolAddress(&p_idx_dp, g_idx_dp);
    cudaGetSymbolAddress(&p_bsums_pd, g_bsums_pd);
    cudaGetSymbolAddress(&p_bsums_dp, g_bsums_dp);
    cudaGetSymbolAddress(&p_hd1, g_hd1);
    cudaGetSymbolAddress(&p_hd2, g_hd2);
    cudaGetSymbolAddress(&p_hp1, g_hp1);
    cudaGetSymbolAddress(&p_hp2, g_hp2);
    cudaGetSymbolAddress(&p_Bimg, g_Bimg);

    cudaFuncSetAttribute(gconv_hmma, cudaFuncAttributeMaxDynamicSharedMemorySize, GCONV_SMEM);

    // preprocessing
    cudaMemsetAsync(p_deg_pd_src, 0, NP * sizeof(int), 0);
    cudaMemsetAsync(p_deg_pd_dst, 0, ND * sizeof(int), 0);
    cudaMemsetAsync(p_deg_dp_src, 0, ND * sizeof(int), 0);
    cudaMemsetAsync(p_deg_dp_dst, 0, NP * sizeof(int), 0);

    hist_kernel<<<(NE + 1023) / 1024, 1024>>>(pd_src, pd_dst, dp_src, dp_dst);
    rs_kernel<<<(NP + 255) / 256, 256>>>();

    {
        int nb_pd = (ND + 1023) / 1024;
        scan_partial<<<nb_pd, 1024>>>((const int*)p_deg_pd_dst, ND, (int*)p_bsums_pd);
        scan_bsums_exclusive<<<1, 1024>>>((int*)p_bsums_pd, nb_pd);
        scan_write<<<nb_pd, 1024>>>((const int*)p_deg_pd_dst, ND, (const int*)p_bsums_pd,
                                    (int*)p_off_pd, (int*)p_cur_pd);
        int nb_dp = (NP + 1023) / 1024;
        scan_partial<<<nb_dp, 1024>>>((const int*)p_deg_dp_dst, NP, (int*)p_bsums_dp);
        scan_bsums_exclusive<<<1, 1024>>>((int*)p_bsums_dp, nb_dp);
        scan_write<<<nb_dp, 1024>>>((const int*)p_deg_dp_dst, NP, (const int*)p_bsums_dp,
                                    (int*)p_off_dp, (int*)p_cur_dp);
    }

    scatter_kernel<<<(NE + 1023) / 1024, 1024>>>(pd_src, pd_dst, (int*)p_cur_pd, (int*)p_idx_pd);
    scatter_kernel<<<(NE + 1023) / 1024, 1024>>>(dp_src, dp_dst, (int*)p_cur_dp, (int*)p_idx_dp);

    build_B<<<6, 256>>>(W1_pd, W1_dp, W2_pd, W2_dp, W3_pd, W3_dp);

    const unsigned char* Bi = (const unsigned char*)p_Bimg;
    const int gpd = (ND + TILE_M - 1) / TILE_M;   // 782
    const int gdp = (NP + TILE_M - 1) / TILE_M;   // 1563

    // Layer 1
    gconv_hmma<<<gpd, 256, GCONV_SMEM>>>(h_p, (const int*)p_off_pd, (const int*)p_idx_pd,
                                         (const float*)p_rs_pd_src, (const float*)p_rs_pd_dst,
                                         Bi + 0 * 65536, b1_pd, (float*)p_hd1, ND);
    gconv_hmma<<<gdp, 256, GCONV_SMEM>>>(h_d, (const int*)p_off_dp, (const int*)p_idx_dp,
                                         (const float*)p_rs_dp_src, (const float*)p_rs_dp_dst,
                                         Bi + 1 * 65536, b1_dp, (float*)p_hp1, NP);
    // Layer 2
    gconv_hmma<<<gpd, 256, GCONV_SMEM>>>((const float*)p_hp1, (const int*)p_off_pd, (const int*)p_idx_pd,
                                         (const float*)p_rs_pd_src, (const float*)p_rs_pd_dst,
                                         Bi + 2 * 65536, b2_pd, (float*)p_hd2, ND);
    gconv_hmma<<<gdp, 256, GCONV_SMEM>>>((const float*)p_hd1, (const int*)p_off_dp, (const int*)p_idx_dp,
                                         (const float*)p_rs_dp_src, (const float*)p_rs_dp_dst,
                                         Bi + 3 * 65536, b2_dp, (float*)p_hp2, NP);
    // Layer 3
    gconv_hmma<<<gpd, 256, GCONV_SMEM>>>((const float*)p_hp2, (const int*)p_off_pd, (const int*)p_idx_pd,
                                         (const float*)p_rs_pd_src, (const float*)p_rs_pd_dst,
                                         Bi + 4 * 65536, b3_pd, out_d, ND);
    gconv_hmma<<<gdp, 256, GCONV_SMEM>>>((const float*)p_hd2, (const int*)p_off_dp, (const int*)p_idx_dp,
                                         (const float*)p_rs_dp_src, (const float*)p_rs_dp_dst,
                                         Bi + 5 * 65536, b3_dp, out_p, NP);
}